// round 1
// baseline (speedup 1.0000x reference)
#include <cuda_runtime.h>
#include <math.h>

#define B_    8
#define C_    256
#define CQ    32
#define NPIX  4096
#define PROJ_ROWS 320   // q rows [0,32), k rows [32,64), v rows [64,320)

// 8 * 320 * 4096 floats = 42 MB scratch for q/k/v projections
__device__ float g_proj[(size_t)B_ * PROJ_ROWS * NPIX];

// ---------------------------------------------------------------------------
// K1: fused QKV projection.  out[o,n] = sum_c W[o,c] * x[b,c,n] + bias[o]
// Tiles: 64(o) x 64(n) x 32(k).  256 threads, 4x4 per thread.
// ---------------------------------------------------------------------------
__global__ void proj_kernel(const float* __restrict__ x,
                            const float* __restrict__ Wq, const float* __restrict__ bq,
                            const float* __restrict__ Wk, const float* __restrict__ bk,
                            const float* __restrict__ Wv, const float* __restrict__ bv) {
    __shared__ float As[64 * 32];
    __shared__ __align__(16) float Xs[32 * 64];

    const int b  = blockIdx.z;
    const int o0 = blockIdx.y * 64;
    const int n0 = blockIdx.x * 64;
    const int tid = threadIdx.x;
    const int tx = tid & 15;
    const int ty = tid >> 4;

    const float* xb = x + (size_t)b * C_ * NPIX;
    float acc[4][4] = {};

    for (int k0 = 0; k0 < C_; k0 += 32) {
        // Load W tile (64 o x 32 c)
        {
            const int o = tid >> 2;           // 0..63
            const int c = (tid & 3) * 8;      // 0,8,16,24
            const int go = o0 + o;
            const float* Wrow;
            if (go < 32)       Wrow = Wq + go * C_;
            else if (go < 64)  Wrow = Wk + (go - 32) * C_;
            else               Wrow = Wv + (go - 64) * C_;
            #pragma unroll
            for (int u = 0; u < 8; ++u) As[o * 32 + c + u] = Wrow[k0 + c + u];
        }
        // Load x tile (32 c x 64 n)
        {
            const int kk = tid >> 3;          // 0..31
            const int nj = (tid & 7) * 8;     // 0..56
            const float* xr = xb + (size_t)(k0 + kk) * NPIX + n0 + nj;
            #pragma unroll
            for (int u = 0; u < 8; ++u) Xs[kk * 64 + nj + u] = xr[u];
        }
        __syncthreads();
        #pragma unroll
        for (int kk = 0; kk < 32; ++kk) {
            float4 xv = *(const float4*)&Xs[kk * 64 + tx * 4];
            #pragma unroll
            for (int ii = 0; ii < 4; ++ii) {
                float a = As[(ty * 4 + ii) * 32 + kk];
                acc[ii][0] += a * xv.x;
                acc[ii][1] += a * xv.y;
                acc[ii][2] += a * xv.z;
                acc[ii][3] += a * xv.w;
            }
        }
        __syncthreads();
    }

    #pragma unroll
    for (int ii = 0; ii < 4; ++ii) {
        const int o = o0 + ty * 4 + ii;
        float bias = (o < 32) ? bq[o] : (o < 64) ? bk[o - 32] : bv[o - 64];
        float* dst = g_proj + ((size_t)b * PROJ_ROWS + o) * NPIX + n0 + tx * 4;
        #pragma unroll
        for (int jj = 0; jj < 4; ++jj) dst[jj] = acc[ii][jj] + bias;
    }
}

// ---------------------------------------------------------------------------
// K2: energy[n,m] = sum_{c<32} q[c,n] * k[c,m].  64x64 tile, K=32 one pass.
// ---------------------------------------------------------------------------
__global__ void energy_kernel(float* __restrict__ att) {
    __shared__ __align__(16) float Qs[32 * 64];
    __shared__ __align__(16) float Ks[32 * 64];

    const int b  = blockIdx.z;
    const int m0 = blockIdx.x * 64;
    const int n0 = blockIdx.y * 64;
    const int tid = threadIdx.x;
    const int tx = tid & 15;
    const int ty = tid >> 4;

    const float* pb = g_proj + (size_t)b * PROJ_ROWS * NPIX;
    {
        const int c  = tid >> 3;           // 0..31
        const int nj = (tid & 7) * 8;
        const float* qr = pb + (size_t)c * NPIX + n0 + nj;
        const float* kr = pb + (size_t)(32 + c) * NPIX + m0 + nj;
        #pragma unroll
        for (int u = 0; u < 8; ++u) {
            Qs[c * 64 + nj + u] = qr[u];
            Ks[c * 64 + nj + u] = kr[u];
        }
    }
    __syncthreads();

    float acc[4][4] = {};
    #pragma unroll
    for (int cc = 0; cc < 32; ++cc) {
        float4 qv = *(const float4*)&Qs[cc * 64 + ty * 4];
        float4 kv = *(const float4*)&Ks[cc * 64 + tx * 4];
        float qr[4] = {qv.x, qv.y, qv.z, qv.w};
        float kr[4] = {kv.x, kv.y, kv.z, kv.w};
        #pragma unroll
        for (int i = 0; i < 4; ++i)
            #pragma unroll
            for (int j = 0; j < 4; ++j)
                acc[i][j] += qr[i] * kr[j];
    }

    #pragma unroll
    for (int ii = 0; ii < 4; ++ii) {
        float4 v4 = make_float4(acc[ii][0], acc[ii][1], acc[ii][2], acc[ii][3]);
        *(float4*)&att[(size_t)b * NPIX * NPIX + (size_t)(n0 + ty * 4 + ii) * NPIX + m0 + tx * 4] = v4;
    }
}

// ---------------------------------------------------------------------------
// K3: in-place row softmax over 4096 elements.  One block (256 thr) per row,
// values kept in registers (single read + single write of the row).
// ---------------------------------------------------------------------------
__global__ void softmax_kernel(float* __restrict__ att) {
    const int n = blockIdx.x;
    const int b = blockIdx.y;
    float* row = att + ((size_t)b * NPIX + n) * NPIX;
    const int t = threadIdx.x;

    float v[16];
    float mx = -1e30f;
    #pragma unroll
    for (int i = 0; i < 16; ++i) {
        v[i] = row[t + i * 256];
        mx = fmaxf(mx, v[i]);
    }
    __shared__ float redm[8];
    #pragma unroll
    for (int o = 16; o; o >>= 1) mx = fmaxf(mx, __shfl_xor_sync(0xFFFFFFFFu, mx, o));
    if ((t & 31) == 0) redm[t >> 5] = mx;
    __syncthreads();
    mx = redm[0];
    #pragma unroll
    for (int w = 1; w < 8; ++w) mx = fmaxf(mx, redm[w]);

    float s = 0.f;
    #pragma unroll
    for (int i = 0; i < 16; ++i) {
        v[i] = expf(v[i] - mx);
        s += v[i];
    }
    __shared__ float reds[8];
    #pragma unroll
    for (int o = 16; o; o >>= 1) s += __shfl_xor_sync(0xFFFFFFFFu, s, o);
    if ((t & 31) == 0) reds[t >> 5] = s;
    __syncthreads();
    s = 0.f;
    #pragma unroll
    for (int w = 0; w < 8; ++w) s += reds[w];
    const float inv = 1.0f / s;
    #pragma unroll
    for (int i = 0; i < 16; ++i) row[t + i * 256] = v[i] * inv;
}

// ---------------------------------------------------------------------------
// K4: out_final[c,n] = 0.5*gamma * sum_m v[c,m]*att[n,m]  +  x[c,n]
// Classic 128x128x8 SGEMM: 256 threads, 8x8 microtiles via float4 smem reads.
// Rows = n (att row-major over m), Cols = c (v row-major over m, transposed
// into smem).
// ---------------------------------------------------------------------------
__global__ void av_kernel(const float* __restrict__ att, const float* __restrict__ x,
                          const float* __restrict__ gamma, float* __restrict__ out) {
    __shared__ __align__(16) float As[8 * 128];
    __shared__ __align__(16) float Bs[8 * 128];

    const int b  = blockIdx.z;
    const int c0 = blockIdx.y * 128;
    const int n0 = blockIdx.x * 128;
    const int tid = threadIdx.x;
    const int tx = tid & 15;
    const int ty = tid >> 4;

    const float* attb = att + (size_t)b * NPIX * NPIX;
    const float* vb   = g_proj + ((size_t)b * PROJ_ROWS + 64) * NPIX;

    const int lr = tid >> 1;         // 0..127
    const int lg = (tid & 1) * 4;    // 0 or 4

    float acc[8][8] = {};

    for (int m0 = 0; m0 < NPIX; m0 += 8) {
        float4 a4 = *(const float4*)&attb[(size_t)(n0 + lr) * NPIX + m0 + lg];
        float4 b4 = *(const float4*)&vb[(size_t)(c0 + lr) * NPIX + m0 + lg];
        As[(lg + 0) * 128 + lr] = a4.x;
        As[(lg + 1) * 128 + lr] = a4.y;
        As[(lg + 2) * 128 + lr] = a4.z;
        As[(lg + 3) * 128 + lr] = a4.w;
        Bs[(lg + 0) * 128 + lr] = b4.x;
        Bs[(lg + 1) * 128 + lr] = b4.y;
        Bs[(lg + 2) * 128 + lr] = b4.z;
        Bs[(lg + 3) * 128 + lr] = b4.w;
        __syncthreads();

        #pragma unroll
        for (int kk = 0; kk < 8; ++kk) {
            float4 a0 = *(const float4*)&As[kk * 128 + ty * 4];
            float4 a1 = *(const float4*)&As[kk * 128 + 64 + ty * 4];
            float4 b0 = *(const float4*)&Bs[kk * 128 + tx * 4];
            float4 b1 = *(const float4*)&Bs[kk * 128 + 64 + tx * 4];
            float ar[8] = {a0.x, a0.y, a0.z, a0.w, a1.x, a1.y, a1.z, a1.w};
            float br[8] = {b0.x, b0.y, b0.z, b0.w, b1.x, b1.y, b1.z, b1.w};
            #pragma unroll
            for (int i = 0; i < 8; ++i)
                #pragma unroll
                for (int j = 0; j < 8; ++j)
                    acc[i][j] += ar[i] * br[j];
        }
        __syncthreads();
    }

    const float g = 0.5f * gamma[0];
    const float* xb = x   + (size_t)b * C_ * NPIX;
    float*       ob = out + (size_t)b * C_ * NPIX;
    #pragma unroll
    for (int i = 0; i < 8; ++i) {
        const int n = n0 + ((i < 4) ? (ty * 4 + i) : (64 + ty * 4 + i - 4));
        #pragma unroll
        for (int j = 0; j < 8; ++j) {
            const int c = c0 + ((j < 4) ? (tx * 4 + j) : (64 + tx * 4 + j - 4));
            const size_t off = (size_t)c * NPIX + n;
            ob[off] = g * acc[i][j] + xb[off];
        }
    }
}

// ---------------------------------------------------------------------------
extern "C" void kernel_launch(void* const* d_in, const int* in_sizes, int n_in,
                              void* d_out, int out_size) {
    const float* x     = (const float*)d_in[0];
    const float* Wq    = (const float*)d_in[1];
    const float* bq    = (const float*)d_in[2];
    const float* Wk    = (const float*)d_in[3];
    const float* bk    = (const float*)d_in[4];
    const float* Wv    = (const float*)d_in[5];
    const float* bv    = (const float*)d_in[6];
    const float* gamma = (const float*)d_in[7];

    float* out = (float*)d_out;
    float* att = out + (size_t)B_ * C_ * NPIX;   // attention region doubles as energy scratch

    proj_kernel<<<dim3(64, 5, B_), 256>>>(x, Wq, bq, Wk, bk, Wv, bv);
    energy_kernel<<<dim3(64, 64, B_), 256>>>(att);
    softmax_kernel<<<dim3(NPIX, B_), 256>>>(att);
    av_kernel<<<dim3(32, 2, B_), 256>>>(att, x, gamma, out);
}

// round 5
// speedup vs baseline: 2.0702x; 2.0702x over previous
#include <cuda_runtime.h>
#include <cuda_bf16.h>
#include <mma.h>
#include <math.h>

#define B_    8
#define C_    256
#define NPIX  4096
#define SROW  48

using namespace nvcuda;

__device__ float          g_qk[(size_t)B_ * 64 * NPIX];
__device__ __nv_bfloat16  g_vb[(size_t)B_ * C_ * NPIX];
__device__ __nv_bfloat16  g_attb[(size_t)B_ * NPIX * NPIX];

// ---------------------------------------------------------------------------
// K1: fused QKV projection. q/k rows to g_qk (fp32), v rows to g_vb (bf16)
// ---------------------------------------------------------------------------
__global__ void proj_kernel(const float* __restrict__ x,
                            const float* __restrict__ Wq, const float* __restrict__ bq,
                            const float* __restrict__ Wk, const float* __restrict__ bk,
                            const float* __restrict__ Wv, const float* __restrict__ bv) {
    __shared__ float As[64 * 32];
    __shared__ __align__(16) float Xs[32 * 64];

    const int b  = blockIdx.z;
    const int o0 = blockIdx.y * 64;
    const int n0 = blockIdx.x * 64;
    const int tid = threadIdx.x;
    const int tx = tid & 15;
    const int ty = tid >> 4;

    const float* xb = x + (size_t)b * C_ * NPIX;
    float acc[4][4] = { };

    for (int k0 = 0; k0 < C_; k0 += 32) {
        const int wo = tid >> 2;
        const int wcid = (tid & 3) * 8;
        const int go = o0 + wo;
        const float* Wrow;
        if (go < 32) {
            Wrow = Wq + go * C_;
        } else if (go < 64) {
            Wrow = Wk + (go - 32) * C_;
        } else {
            Wrow = Wv + (go - 64) * C_;
        }
        #pragma unroll
        for (int u = 0; u < 8; ++u) As[wo * 32 + wcid + u] = Wrow[k0 + wcid + u];

        const int kk2 = tid >> 3;
        const int nj2 = (tid & 7) * 8;
        const float* xr = xb + (size_t)(k0 + kk2) * NPIX + n0 + nj2;
        #pragma unroll
        for (int u = 0; u < 8; ++u) Xs[kk2 * 64 + nj2 + u] = xr[u];

        __syncthreads();
        #pragma unroll
        for (int kk = 0; kk < 32; ++kk) {
            float4 xv = *(const float4*)&Xs[kk * 64 + tx * 4];
            #pragma unroll
            for (int ii = 0; ii < 4; ++ii) {
                float a = As[(ty * 4 + ii) * 32 + kk];
                acc[ii][0] += a * xv.x;
                acc[ii][1] += a * xv.y;
                acc[ii][2] += a * xv.z;
                acc[ii][3] += a * xv.w;
            }
        }
        __syncthreads();
    }

    #pragma unroll
    for (int ii = 0; ii < 4; ++ii) {
        const int o = o0 + ty * 4 + ii;
        float bias;
        if (o < 32) {
            bias = bq[o];
        } else if (o < 64) {
            bias = bk[o - 32];
        } else {
            bias = bv[o - 64];
        }
        if (o < 64) {
            float* dst = g_qk + ((size_t)b * 64 + o) * NPIX + n0 + tx * 4;
            #pragma unroll
            for (int jj = 0; jj < 4; ++jj) dst[jj] = acc[ii][jj] + bias;
        } else {
            __nv_bfloat16* dst = g_vb + ((size_t)b * C_ + (o - 64)) * NPIX + n0 + tx * 4;
            #pragma unroll
            for (int jj = 0; jj < 4; ++jj) dst[jj] = __float2bfloat16(acc[ii][jj] + bias);
        }
    }
}

// ---------------------------------------------------------------------------
// K2: energy[n,m] = sum over c<32 of q[c,n]*k[c,m]
// ---------------------------------------------------------------------------
__global__ void energy_kernel(float* __restrict__ att) {
    __shared__ __align__(16) float Qs[32 * 64];
    __shared__ __align__(16) float Ks[32 * 64];

    const int b  = blockIdx.z;
    const int m0 = blockIdx.x * 64;
    const int n0 = blockIdx.y * 64;
    const int tid = threadIdx.x;
    const int tx = tid & 15;
    const int ty = tid >> 4;

    const float* pb = g_qk + (size_t)b * 64 * NPIX;
    const int cld  = tid >> 3;
    const int njld = (tid & 7) * 8;
    const float* qr = pb + (size_t)cld * NPIX + n0 + njld;
    const float* kr = pb + (size_t)(32 + cld) * NPIX + m0 + njld;
    #pragma unroll
    for (int u = 0; u < 8; ++u) {
        Qs[cld * 64 + njld + u] = qr[u];
        Ks[cld * 64 + njld + u] = kr[u];
    }
    __syncthreads();

    float acc[4][4] = { };
    #pragma unroll
    for (int cc = 0; cc < 32; ++cc) {
        float4 qv = *(const float4*)&Qs[cc * 64 + ty * 4];
        float4 kv = *(const float4*)&Ks[cc * 64 + tx * 4];
        float qreg[4];
        float kreg[4];
        qreg[0] = qv.x; qreg[1] = qv.y; qreg[2] = qv.z; qreg[3] = qv.w;
        kreg[0] = kv.x; kreg[1] = kv.y; kreg[2] = kv.z; kreg[3] = kv.w;
        #pragma unroll
        for (int i = 0; i < 4; ++i) {
            #pragma unroll
            for (int j = 0; j < 4; ++j) acc[i][j] += qreg[i] * kreg[j];
        }
    }

    #pragma unroll
    for (int ii = 0; ii < 4; ++ii) {
        float4 v4 = make_float4(acc[ii][0], acc[ii][1], acc[ii][2], acc[ii][3]);
        *(float4*)&att[(size_t)b * NPIX * NPIX + (size_t)(n0 + ty * 4 + ii) * NPIX + m0 + tx * 4] = v4;
    }
}

// ---------------------------------------------------------------------------
// K3: in-place row softmax plus bf16 copy of the probabilities.
// ---------------------------------------------------------------------------
__global__ void softmax_kernel(float* __restrict__ att) {
    const int n = blockIdx.x;
    const int b = blockIdx.y;
    float* row = att + ((size_t)b * NPIX + n) * NPIX;
    __nv_bfloat16* rowb = g_attb + ((size_t)b * NPIX + n) * NPIX;
    const int t = threadIdx.x;

    float v[16];
    float mx = -1e30f;
    #pragma unroll
    for (int i = 0; i < 16; ++i) {
        v[i] = row[t + i * 256];
        mx = fmaxf(mx, v[i]);
    }
    __shared__ float redm[8];
    #pragma unroll
    for (int o = 16; o; o >>= 1) mx = fmaxf(mx, __shfl_xor_sync(0xFFFFFFFFu, mx, o));
    if ((t & 31) == 0) redm[t >> 5] = mx;
    __syncthreads();
    mx = redm[0];
    #pragma unroll
    for (int w = 1; w < 8; ++w) mx = fmaxf(mx, redm[w]);

    float s = 0.f;
    #pragma unroll
    for (int i = 0; i < 16; ++i) {
        v[i] = expf(v[i] - mx);
        s += v[i];
    }
    __shared__ float reds[8];
    #pragma unroll
    for (int o = 16; o; o >>= 1) s += __shfl_xor_sync(0xFFFFFFFFu, s, o);
    if ((t & 31) == 0) reds[t >> 5] = s;
    __syncthreads();
    s = 0.f;
    #pragma unroll
    for (int w = 0; w < 8; ++w) s += reds[w];
    const float inv = 1.0f / s;
    #pragma unroll
    for (int i = 0; i < 16; ++i) {
        float p = v[i] * inv;
        row[t + i * 256]  = p;
        rowb[t + i * 256] = __float2bfloat16(p);
    }
}

// ---------------------------------------------------------------------------
// K4: tensor-core AV GEMM via WMMA (no inline asm).
//   D[c,n] = sum_m v[c,m] * att[n,m]  (bf16 in, fp32 acc)
//   out[c,n] = 0.5*gamma*D + x[c,n]
// CTA tile 128c x 128n, 8 warps each 32c x 64n (2x4 fragments of 16x16).
// v tile [c][k] row_major A; att tile [n][k] is col_major B (B(k,n)=att[n][k]).
// ---------------------------------------------------------------------------
__global__ void __launch_bounds__(256, 2)
av_wmma_kernel(const float* __restrict__ x, const float* __restrict__ gamma,
               float* __restrict__ out) {
    __shared__ __align__(256) __nv_bfloat16 As[2][128 * SROW];
    __shared__ __align__(256) __nv_bfloat16 Bs[2][128 * SROW];

    const int b    = blockIdx.z;
    const int c0   = blockIdx.y * 128;
    const int n0   = blockIdx.x * 128;
    const int tid  = threadIdx.x;
    const int warp = tid >> 5;
    const int lane = tid & 31;
    const int wc   = (warp & 3) * 32;
    const int wn   = (warp >> 2) * 64;

    const __nv_bfloat16* vb = g_vb   + (size_t)b * C_ * NPIX;
    const __nv_bfloat16* ab = g_attb + (size_t)b * NPIX * NPIX;

    const int lrow  = tid >> 1;
    const int lhalf = (tid & 1) * 16;
    const __nv_bfloat16* gA = vb + (size_t)(c0 + lrow) * NPIX + lhalf;
    const __nv_bfloat16* gB = ab + (size_t)(n0 + lrow) * NPIX + lhalf;
    const int sOff = lrow * SROW + lhalf;

    wmma::fragment<wmma::accumulator, 16, 16, 16, float> acc[2][4];
    #pragma unroll
    for (int i = 0; i < 2; ++i) {
        #pragma unroll
        for (int j = 0; j < 4; ++j) wmma::fill_fragment(acc[i][j], 0.0f);
    }

    uint4 pa0 = *(const uint4*)(gA);
    uint4 pa1 = *(const uint4*)(gA + 8);
    uint4 pb0 = *(const uint4*)(gB);
    uint4 pb1 = *(const uint4*)(gB + 8);
    *(uint4*)&As[0][sOff]     = pa0;
    *(uint4*)&As[0][sOff + 8] = pa1;
    *(uint4*)&Bs[0][sOff]     = pb0;
    *(uint4*)&Bs[0][sOff + 8] = pb1;
    __syncthreads();

    for (int it = 0; it < 128; ++it) {
        const int cur = it & 1;
        uint4 na0, na1, nb0, nb1;
        if (it < 127) {
            const __nv_bfloat16* pA = gA + (it + 1) * 32;
            const __nv_bfloat16* pB = gB + (it + 1) * 32;
            na0 = *(const uint4*)(pA);
            na1 = *(const uint4*)(pA + 8);
            nb0 = *(const uint4*)(pB);
            nb1 = *(const uint4*)(pB + 8);
        }

        const __nv_bfloat16* Ab = &As[cur][0];
        const __nv_bfloat16* Bb = &Bs[cur][0];

        #pragma unroll
        for (int kk = 0; kk < 32; kk += 16) {
            wmma::fragment<wmma::matrix_a, 16, 16, 16, __nv_bfloat16, wmma::row_major> afrag[2];
            wmma::fragment<wmma::matrix_b, 16, 16, 16, __nv_bfloat16, wmma::col_major> bfrag[4];
            #pragma unroll
            for (int i = 0; i < 2; ++i) {
                wmma::load_matrix_sync(afrag[i], Ab + (wc + 16 * i) * SROW + kk, SROW);
            }
            #pragma unroll
            for (int j = 0; j < 4; ++j) {
                wmma::load_matrix_sync(bfrag[j], Bb + (wn + 16 * j) * SROW + kk, SROW);
            }
            #pragma unroll
            for (int i = 0; i < 2; ++i) {
                #pragma unroll
                for (int j = 0; j < 4; ++j) {
                    wmma::mma_sync(acc[i][j], afrag[i], bfrag[j], acc[i][j]);
                }
            }
        }

        if (it < 127) {
            const int nxt = cur ^ 1;
            *(uint4*)&As[nxt][sOff]     = na0;
            *(uint4*)&As[nxt][sOff + 8] = na1;
            *(uint4*)&Bs[nxt][sOff]     = nb0;
            *(uint4*)&Bs[nxt][sOff + 8] = nb1;
        }
        __syncthreads();
    }

    // Epilogue: stage each 16x16 fragment in smem, fuse 0.5*gamma*D + x.
    const float g = 0.5f * gamma[0];
    const float* xb = x   + (size_t)b * C_ * NPIX;
    float*       ob = out + (size_t)b * C_ * NPIX;
    float* stage = (float*)(&As[0][0]) + warp * 256;

    const int srow = lane >> 1;
    const int scol = (lane & 1) * 8;

    #pragma unroll
    for (int i = 0; i < 2; ++i) {
        #pragma unroll
        for (int j = 0; j < 4; ++j) {
            wmma::store_matrix_sync(stage, acc[i][j], 16, wmma::mem_row_major);
            __syncwarp();
            const int cc = c0 + wc + 16 * i + srow;
            const int nn = n0 + wn + 16 * j + scol;
            const size_t off = (size_t)cc * NPIX + nn;
            float4 s0 = *(const float4*)&stage[srow * 16 + scol];
            float4 s1 = *(const float4*)&stage[srow * 16 + scol + 4];
            float4 xv0 = *(const float4*)&xb[off];
            float4 xv1 = *(const float4*)&xb[off + 4];
            float4 ov0;
            float4 ov1;
            ov0.x = g * s0.x + xv0.x;
            ov0.y = g * s0.y + xv0.y;
            ov0.z = g * s0.z + xv0.z;
            ov0.w = g * s0.w + xv0.w;
            ov1.x = g * s1.x + xv1.x;
            ov1.y = g * s1.y + xv1.y;
            ov1.z = g * s1.z + xv1.z;
            ov1.w = g * s1.w + xv1.w;
            *(float4*)&ob[off]     = ov0;
            *(float4*)&ob[off + 4] = ov1;
            __syncwarp();
        }
    }
}

// ---------------------------------------------------------------------------
extern "C" void kernel_launch(void* const* d_in, const int* in_sizes, int n_in,
                              void* d_out, int out_size) {
    const float* x     = (const float*)d_in[0];
    const float* Wq    = (const float*)d_in[1];
    const float* bq    = (const float*)d_in[2];
    const float* Wk    = (const float*)d_in[3];
    const float* bk    = (const float*)d_in[4];
    const float* Wv    = (const float*)d_in[5];
    const float* bv    = (const float*)d_in[6];
    const float* gamma = (const float*)d_in[7];

    float* out = (float*)d_out;
    float* att = out + (size_t)B_ * C_ * NPIX;

    proj_kernel<<<dim3(64, 5, B_), 256>>>(x, Wq, bq, Wk, bk, Wv, bv);
    energy_kernel<<<dim3(64, 64, B_), 256>>>(att);
    softmax_kernel<<<dim3(NPIX, B_), 256>>>(att);
    av_wmma_kernel<<<dim3(32, 2, B_), 256>>>(x, gamma, out);
}